// round 6
// baseline (speedup 1.0000x reference)
#include <cuda_runtime.h>
#include <cuda_fp16.h>

#define NN   50000
#define EE   800000
#define HID  64
#define IND  128
#define OUTD 40
#define NBLK ((NN + 255) / 256)   // 196 scan blocks
#define GB   ((NN + 63) / 64)     // 782 gemm blocks
#define HB   ((EE + 255) / 256)   // 3125 edge blocks

// ---------------- device scratch (no allocations allowed) ----------------
__device__ __half g_hlin[NN * HID];     // linear-transformed features (fp16 storage)
__device__ float g_h0[NN * HID];        // layer outputs (JK cat members, fp32)
__device__ float g_h1[NN * HID];
__device__ float g_h2[NN * HID];
__device__ int   g_rowptr[NN + 1];      // CSC row pointers (by dst)
__device__ int   g_cnt[NN];             // histogram / fill cursors
__device__ int   g_bsum[NBLK];          // per-block sums -> exclusive offsets
__device__ int2  g_edge[EE];            // (src, weight-bits) grouped by dst
__device__ int   g_is64;                // edge_index dtype flag (1 = int64, 0 = int32)

__device__ __forceinline__ float* buf_sel(int s) {
    switch (s) {
        case 1:  return g_h0;
        case 2:  return g_h1;
        default: return g_h2;
    }
}

__device__ __forceinline__ int clampN(int v) {
    return (v < 0) ? 0 : ((v >= NN) ? NN - 1 : v);
}

__device__ __forceinline__ int edge_at(const int* __restrict__ p32, int row, int e, int is64) {
    long long idx = (long long)row * EE + e;
    return is64 ? p32[2 * idx] : p32[idx];
}

// ---------------- zero counters + dtype detect (fused) ----------------
__global__ void zero_detect_kernel(const int* __restrict__ p32) {
    int i = blockIdx.x * blockDim.x + threadIdx.x;
    if (i < NN) g_cnt[i] = 0;
    if (blockIdx.x == 0 && threadIdx.x < 32) {
        int lane = threadIdx.x;
        int any = p32[2 * lane + 1] | p32[2 * (lane + 32) + 1];
        unsigned nz = __ballot_sync(0xFFFFFFFFu, any != 0);
        if (lane == 0) g_is64 = (nz == 0) ? 1 : 0;
    }
}

// ---------------- combo: gemm layer1 (blocks [0,GB)) + histogram (rest) ----------------
__global__ void __launch_bounds__(256) gemm1_hist_kernel(const float* __restrict__ x,
                                                         const float* __restrict__ W1,
                                                         const int* __restrict__ ei32) {
    __shared__ float ws[IND * 64];
    int tid = threadIdx.x;

    if (blockIdx.x >= GB) {
        // histogram part (independent of gemm)
        int e = (blockIdx.x - GB) * 256 + tid;
        if (e < EE) {
            int d = clampN(edge_at(ei32, 1, e, g_is64));
            atomicAdd(&g_cnt[d], 1);
        }
        return;
    }

    // gemm part: g_hlin[N,64](fp16) = x[N,128] @ W1[128,64]
    for (int i = tid; i < IND * 64; i += 256) ws[i] = W1[i];
    __syncthreads();

    __half2* Y = (__half2*)g_hlin;
    int w = tid >> 5, lane = tid & 31;
    int row0 = blockIdx.x * 64 + w * 8;

    const float* xp[8];
#pragma unroll
    for (int i = 0; i < 8; i++) {
        int r = row0 + i;
        if (r >= NN) r = NN - 1;
        xp[i] = x + (size_t)r * IND;
    }

    float acc0[8], acc1[8];
#pragma unroll
    for (int i = 0; i < 8; i++) { acc0[i] = 0.f; acc1[i] = 0.f; }

#pragma unroll 4
    for (int k = 0; k < IND; k += 4) {
        float2 wv0 = *(const float2*)&ws[(k + 0) * 64 + lane * 2];
        float2 wv1 = *(const float2*)&ws[(k + 1) * 64 + lane * 2];
        float2 wv2 = *(const float2*)&ws[(k + 2) * 64 + lane * 2];
        float2 wv3 = *(const float2*)&ws[(k + 3) * 64 + lane * 2];
#pragma unroll
        for (int i = 0; i < 8; i++) {
            float4 xv = *(const float4*)(xp[i] + k);
            acc0[i] = fmaf(xv.x, wv0.x, acc0[i]); acc1[i] = fmaf(xv.x, wv0.y, acc1[i]);
            acc0[i] = fmaf(xv.y, wv1.x, acc0[i]); acc1[i] = fmaf(xv.y, wv1.y, acc1[i]);
            acc0[i] = fmaf(xv.z, wv2.x, acc0[i]); acc1[i] = fmaf(xv.z, wv2.y, acc1[i]);
            acc0[i] = fmaf(xv.w, wv3.x, acc0[i]); acc1[i] = fmaf(xv.w, wv3.y, acc1[i]);
        }
    }

#pragma unroll
    for (int i = 0; i < 8; i++) {
        int r = row0 + i;
        if (r < NN)
            Y[(size_t)r * 32 + lane] = __floats2half2_rn(acc0[i], acc1[i]);
    }
}

// ---------------- multi-block scan ----------------
__device__ __forceinline__ int block_excl_scan_256(int v, int tid) {
    int lane = tid & 31, w = tid >> 5;
    int x = v;
#pragma unroll
    for (int o = 1; o < 32; o <<= 1) {
        int y = __shfl_up_sync(0xFFFFFFFFu, x, o);
        if (lane >= o) x += y;
    }
    __shared__ int wsum[8];
    if (lane == 31) wsum[w] = x;
    __syncthreads();
    if (w == 0) {
        int s = (lane < 8) ? wsum[lane] : 0;
#pragma unroll
        for (int o = 1; o < 8; o <<= 1) {
            int y = __shfl_up_sync(0xFFFFFFFFu, s, o);
            if (lane >= o) s += y;
        }
        if (lane < 8) wsum[lane] = s;
    }
    __syncthreads();
    int incl = x + ((w > 0) ? wsum[w - 1] : 0);
    return incl - v;
}

__global__ void __launch_bounds__(256) scan_p1_kernel() {
    int i = blockIdx.x * 256 + threadIdx.x;
    int v = (i < NN) ? g_cnt[i] : 0;
#pragma unroll
    for (int o = 16; o > 0; o >>= 1) v += __shfl_down_sync(0xFFFFFFFFu, v, o);
    __shared__ int wsum[8];
    if ((threadIdx.x & 31) == 0) wsum[threadIdx.x >> 5] = v;
    __syncthreads();
    if (threadIdx.x == 0) {
        int s = 0;
#pragma unroll
        for (int w = 0; w < 8; w++) s += wsum[w];
        g_bsum[blockIdx.x] = s;
    }
}

__global__ void __launch_bounds__(256) scan_p2_kernel() {
    int t = threadIdx.x;
    int v = (t < NBLK) ? g_bsum[t] : 0;
    int excl = block_excl_scan_256(v, t);
    if (t < NBLK) g_bsum[t] = excl;
    if (t == NBLK - 1) g_rowptr[NN] = excl + v;
}

__global__ void __launch_bounds__(256) scan_p3_kernel() {
    int i = blockIdx.x * 256 + threadIdx.x;
    int v = (i < NN) ? g_cnt[i] : 0;
    int excl = block_excl_scan_256(v, threadIdx.x);
    if (i < NN) {
        g_rowptr[i] = g_bsum[blockIdx.x] + excl;
        g_cnt[i] = 0;
    }
}

__global__ void fill_kernel(const int* __restrict__ ei32,
                            const float* __restrict__ ew) {
    int e = blockIdx.x * blockDim.x + threadIdx.x;
    if (e < EE) {
        int is64 = g_is64;
        int d = clampN(edge_at(ei32, 1, e, is64));
        int s = clampN(edge_at(ei32, 0, e, is64));
        int pos = g_rowptr[d] + atomicAdd(&g_cnt[d], 1);
        g_edge[pos] = make_int2(s, __float_as_int(ew[e]));
    }
}

// ---------------- dense GEMM (layers 2,3): g_hlin(fp16) = h(fp32) @ W ----------------
template <int K>
__global__ void __launch_bounds__(256) gemm64_kernel(int src_sel,
                                                     const float* __restrict__ W) {
    __shared__ float ws[K * 64];
    int tid = threadIdx.x;
    for (int i = tid; i < K * 64; i += 256) ws[i] = W[i];
    __syncthreads();

    const float* X = buf_sel(src_sel);
    __half2*     Y = (__half2*)g_hlin;

    int w = tid >> 5, lane = tid & 31;
    int row0 = blockIdx.x * 64 + w * 8;

    const float* xp[8];
#pragma unroll
    for (int i = 0; i < 8; i++) {
        int r = row0 + i;
        if (r >= NN) r = NN - 1;
        xp[i] = X + (size_t)r * K;
    }

    float acc0[8], acc1[8];
#pragma unroll
    for (int i = 0; i < 8; i++) { acc0[i] = 0.f; acc1[i] = 0.f; }

#pragma unroll 4
    for (int k = 0; k < K; k += 4) {
        float2 wv0 = *(const float2*)&ws[(k + 0) * 64 + lane * 2];
        float2 wv1 = *(const float2*)&ws[(k + 1) * 64 + lane * 2];
        float2 wv2 = *(const float2*)&ws[(k + 2) * 64 + lane * 2];
        float2 wv3 = *(const float2*)&ws[(k + 3) * 64 + lane * 2];
#pragma unroll
        for (int i = 0; i < 8; i++) {
            float4 xv = *(const float4*)(xp[i] + k);
            acc0[i] = fmaf(xv.x, wv0.x, acc0[i]); acc1[i] = fmaf(xv.x, wv0.y, acc1[i]);
            acc0[i] = fmaf(xv.y, wv1.x, acc0[i]); acc1[i] = fmaf(xv.y, wv1.y, acc1[i]);
            acc0[i] = fmaf(xv.z, wv2.x, acc0[i]); acc1[i] = fmaf(xv.z, wv2.y, acc1[i]);
            acc0[i] = fmaf(xv.w, wv3.x, acc0[i]); acc1[i] = fmaf(xv.w, wv3.y, acc1[i]);
        }
    }

#pragma unroll
    for (int i = 0; i < 8; i++) {
        int r = row0 + i;
        if (r < NN)
            Y[(size_t)r * 32 + lane] = __floats2half2_rn(acc0[i], acc1[i]);
    }
}

// ---------------- aggregation: warp per node, 2-edge unroll, paired edge loads ----------------
__global__ void __launch_bounds__(256) agg_kernel(int dst_sel,
                                                  const float* __restrict__ bias) {
    int gw   = (blockIdx.x * 256 + threadIdx.x) >> 5;
    int lane = threadIdx.x & 31;
    if (gw >= NN) return;

    const __half2* hl = (const __half2*)g_hlin;
    float*         hout = buf_sel(dst_sel);

    int beg = g_rowptr[gw], end = g_rowptr[gw + 1];
    float a0 = 0.f, a1 = 0.f, c0 = 0.f, c1 = 0.f;

    int e = beg;
    for (; e + 2 <= end; e += 2) {
        int2 E0 = g_edge[e];
        int2 E1 = g_edge[e + 1];
        float2 h0 = __half22float2(hl[(size_t)E0.x * 32 + lane]);
        float2 h1 = __half22float2(hl[(size_t)E1.x * 32 + lane]);
        float w0 = __int_as_float(E0.y);
        float w1 = __int_as_float(E1.y);
        a0 = fmaf(w0, h0.x, a0); a1 = fmaf(w0, h0.y, a1);
        c0 = fmaf(w1, h1.x, c0); c1 = fmaf(w1, h1.y, c1);
    }
    if (e < end) {
        int2 E0 = g_edge[e];
        float2 h0 = __half22float2(hl[(size_t)E0.x * 32 + lane]);
        float w0 = __int_as_float(E0.y);
        a0 = fmaf(w0, h0.x, a0); a1 = fmaf(w0, h0.y, a1);
    }
    a0 += c0; a1 += c1;

    float b0 = bias[lane * 2], b1 = bias[lane * 2 + 1];
    float2 o;
    o.x = fmaxf(a0 + b0, 0.f);
    o.y = fmaxf(a1 + b1, 0.f);
    *(float2*)&hout[(size_t)gw * 64 + lane * 2] = o;
}

// ---------------- final: out = [h0|h1|h2] @ Wlin + blin (pad fused via smem) ----------------
__global__ void __launch_bounds__(256) final_kernel(const float* __restrict__ Wlin,
                                                    const float* __restrict__ blin,
                                                    float* __restrict__ out) {
    __shared__ float ws[192 * 64];   // 48 KB: Wlin padded 40 -> 64 cols
    int tid = threadIdx.x;
    for (int i = tid; i < 192 * 64; i += 256) {
        int k = i >> 6, c = i & 63;
        ws[i] = (c < OUTD) ? Wlin[k * OUTD + c] : 0.f;
    }
    __syncthreads();

    int w = tid >> 5, lane = tid & 31;
    int row0 = blockIdx.x * 64 + w * 8;

    int rr[8];
#pragma unroll
    for (int i = 0; i < 8; i++) {
        int r = row0 + i;
        rr[i] = (r < NN) ? r : NN - 1;
    }

    float acc0[8], acc1[8];
#pragma unroll
    for (int i = 0; i < 8; i++) { acc0[i] = 0.f; acc1[i] = 0.f; }

#pragma unroll 1
    for (int l = 0; l < 3; l++) {
        const float* Hp = (l == 0) ? g_h0 : (l == 1) ? g_h1 : g_h2;
        const float* wp = ws + l * 64 * 64;
#pragma unroll 4
        for (int k = 0; k < 64; k += 4) {
            float2 wv0 = *(const float2*)&wp[(k + 0) * 64 + lane * 2];
            float2 wv1 = *(const float2*)&wp[(k + 1) * 64 + lane * 2];
            float2 wv2 = *(const float2*)&wp[(k + 2) * 64 + lane * 2];
            float2 wv3 = *(const float2*)&wp[(k + 3) * 64 + lane * 2];
#pragma unroll
            for (int i = 0; i < 8; i++) {
                float4 xv = *(const float4*)&Hp[(size_t)rr[i] * 64 + k];
                acc0[i] = fmaf(xv.x, wv0.x, acc0[i]); acc1[i] = fmaf(xv.x, wv0.y, acc1[i]);
                acc0[i] = fmaf(xv.y, wv1.x, acc0[i]); acc1[i] = fmaf(xv.y, wv1.y, acc1[i]);
                acc0[i] = fmaf(xv.z, wv2.x, acc0[i]); acc1[i] = fmaf(xv.z, wv2.y, acc1[i]);
                acc0[i] = fmaf(xv.w, wv3.x, acc0[i]); acc1[i] = fmaf(xv.w, wv3.y, acc1[i]);
            }
        }
    }

    int c = lane * 2;
    if (c < OUTD) {
        float b0 = blin[c], b1 = blin[c + 1];
#pragma unroll
        for (int i = 0; i < 8; i++) {
            int r = row0 + i;
            if (r < NN) {
                float2 o; o.x = acc0[i] + b0; o.y = acc1[i] + b1;
                *(float2*)&out[(size_t)r * OUTD + c] = o;
            }
        }
    }
}

// ---------------- launch ----------------
extern "C" void kernel_launch(void* const* d_in, const int* in_sizes, int n_in,
                              void* d_out, int out_size) {
    const float* x    = (const float*)d_in[0];
    const int*   ei32 = (const int*)d_in[1];
    const float* ew   = (const float*)d_in[2];
    const float* W1 = (const float*)d_in[3];
    const float* b1 = (const float*)d_in[4];
    const float* W2 = (const float*)d_in[5];
    const float* b2 = (const float*)d_in[6];
    const float* W3 = (const float*)d_in[7];
    const float* b3 = (const float*)d_in[8];
    const float* Wl = (const float*)d_in[9];
    const float* bl = (const float*)d_in[10];
    float* out = (float*)d_out;

    const int AB = (NN * 32 + 255) / 256;     // 6250

    zero_detect_kernel<<<NBLK, 256>>>(ei32);
    gemm1_hist_kernel<<<GB + HB, 256>>>(x, W1, ei32);   // gemm1 || histogram
    scan_p1_kernel<<<NBLK, 256>>>();
    scan_p2_kernel<<<1, 256>>>();
    scan_p3_kernel<<<NBLK, 256>>>();
    fill_kernel<<<HB, 256>>>(ei32, ew);

    agg_kernel<<<AB, 256>>>(1, b1);

    gemm64_kernel<HID><<<GB, 256>>>(1, W2);
    agg_kernel<<<AB, 256>>>(2, b2);

    gemm64_kernel<HID><<<GB, 256>>>(2, W3);
    agg_kernel<<<AB, 256>>>(3, b3);

    final_kernel<<<GB, 256>>>(Wl, bl, out);
}

// round 7
// speedup vs baseline: 1.4531x; 1.4531x over previous
#include <cuda_runtime.h>
#include <cuda_fp16.h>

#define NN   50000
#define EE   800000
#define HID  64
#define IND  128
#define OUTD 40
#define NBLK ((NN + 255) / 256)   // 196 scan blocks
#define GB   ((NN + 63) / 64)     // 782 gemm blocks
#define HB   ((EE + 255) / 256)   // 3125 edge blocks

// ---------------- device scratch (no allocations allowed) ----------------
__device__ __half g_hlin[NN * HID];     // linear-transformed features (fp16 storage)
__device__ float g_h0[NN * HID];        // layer outputs (JK cat members, fp32)
__device__ float g_h1[NN * HID];
__device__ float g_h2[NN * HID];
__device__ int   g_rowptr[NN + 1];      // CSC row pointers (by dst)
__device__ int   g_cnt[NN];             // histogram / fill cursors
__device__ int   g_bsum[NBLK];          // per-block sums
__device__ int2  g_edge[EE];            // (src, weight-bits) grouped by dst
__device__ int   g_is64;                // edge_index dtype flag (1 = int64, 0 = int32)

__device__ __forceinline__ float* buf_sel(int s) {
    switch (s) {
        case 1:  return g_h0;
        case 2:  return g_h1;
        default: return g_h2;
    }
}

__device__ __forceinline__ int clampN(int v) {
    return (v < 0) ? 0 : ((v >= NN) ? NN - 1 : v);
}

__device__ __forceinline__ int edge_at(const int* __restrict__ p32, int row, int e, int is64) {
    long long idx = (long long)row * EE + e;
    return is64 ? p32[2 * idx] : p32[idx];
}

// ---------------- zero counters + dtype detect (fused) ----------------
__global__ void zero_detect_kernel(const int* __restrict__ p32) {
    int i = blockIdx.x * blockDim.x + threadIdx.x;
    if (i < NN) g_cnt[i] = 0;
    if (blockIdx.x == 0 && threadIdx.x < 32) {
        int lane = threadIdx.x;
        int any = p32[2 * lane + 1] | p32[2 * (lane + 32) + 1];
        unsigned nz = __ballot_sync(0xFFFFFFFFu, any != 0);
        if (lane == 0) g_is64 = (nz == 0) ? 1 : 0;
    }
}

// ---------------- histogram (standalone, no smem, full occupancy) ----------------
__global__ void hist_kernel(const int* __restrict__ ei32) {
    int e = blockIdx.x * blockDim.x + threadIdx.x;
    if (e < EE) {
        int d = clampN(edge_at(ei32, 1, e, g_is64));
        atomicAdd(&g_cnt[d], 1);
    }
}

// ---------------- scan ----------------
__device__ __forceinline__ int block_excl_scan_256(int v, int tid, int* wsum) {
    int lane = tid & 31, w = tid >> 5;
    int x = v;
#pragma unroll
    for (int o = 1; o < 32; o <<= 1) {
        int y = __shfl_up_sync(0xFFFFFFFFu, x, o);
        if (lane >= o) x += y;
    }
    if (lane == 31) wsum[w] = x;
    __syncthreads();
    if (w == 0) {
        int s = (lane < 8) ? wsum[lane] : 0;
#pragma unroll
        for (int o = 1; o < 8; o <<= 1) {
            int y = __shfl_up_sync(0xFFFFFFFFu, s, o);
            if (lane >= o) s += y;
        }
        if (lane < 8) wsum[lane] = s;
    }
    __syncthreads();
    int incl = x + ((w > 0) ? wsum[w - 1] : 0);
    return incl - v;
}

// phase A: per-block chunk sums of g_cnt
__global__ void __launch_bounds__(256) scanA_kernel() {
    int i = blockIdx.x * 256 + threadIdx.x;
    int v = (i < NN) ? g_cnt[i] : 0;
#pragma unroll
    for (int o = 16; o > 0; o >>= 1) v += __shfl_down_sync(0xFFFFFFFFu, v, o);
    __shared__ int wsum[8];
    if ((threadIdx.x & 31) == 0) wsum[threadIdx.x >> 5] = v;
    __syncthreads();
    if (threadIdx.x == 0) {
        int s = 0;
#pragma unroll
        for (int w = 0; w < 8; w++) s += wsum[w];
        g_bsum[blockIdx.x] = s;
    }
}

// phase B: every block redundantly scans the 196 block sums (cheap), then
// does its local exclusive scan, writes rowptr, resets cursors.
__global__ void __launch_bounds__(256) scanB_kernel() {
    __shared__ int wsum[8];
    __shared__ int blk_off;
    int tid = threadIdx.x;

    int v = (tid < NBLK) ? g_bsum[tid] : 0;
    int excl = block_excl_scan_256(v, tid, wsum);
    if (tid == blockIdx.x) blk_off = excl;
    if (blockIdx.x == 0 && tid == NBLK - 1) g_rowptr[NN] = excl + v;
    __syncthreads();

    int i = blockIdx.x * 256 + tid;
    int c = (i < NN) ? g_cnt[i] : 0;
    int ex2 = block_excl_scan_256(c, tid, wsum);
    if (i < NN) {
        g_rowptr[i] = blk_off + ex2;
        g_cnt[i] = 0;
    }
}

__global__ void fill_kernel(const int* __restrict__ ei32,
                            const float* __restrict__ ew) {
    int e = blockIdx.x * blockDim.x + threadIdx.x;
    if (e < EE) {
        int is64 = g_is64;
        int d = clampN(edge_at(ei32, 1, e, is64));
        int s = clampN(edge_at(ei32, 0, e, is64));
        int pos = g_rowptr[d] + atomicAdd(&g_cnt[d], 1);
        g_edge[pos] = make_int2(s, __float_as_int(ew[e]));
    }
}

// ---------------- dense GEMM: g_hlin[N,64](fp16) = X[N,K](fp32) @ W[K,64] ----------------
template <int K>
__global__ void __launch_bounds__(256) gemm64_kernel(const float* __restrict__ xin,
                                                     int src_sel,
                                                     const float* __restrict__ W) {
    __shared__ float ws[K * 64];
    int tid = threadIdx.x;
    for (int i = tid; i < K * 64; i += 256) ws[i] = W[i];
    __syncthreads();

    const float* X = xin ? xin : buf_sel(src_sel);
    __half2*     Y = (__half2*)g_hlin;

    int w = tid >> 5, lane = tid & 31;
    int row0 = blockIdx.x * 64 + w * 8;

    const float* xp[8];
#pragma unroll
    for (int i = 0; i < 8; i++) {
        int r = row0 + i;
        if (r >= NN) r = NN - 1;
        xp[i] = X + (size_t)r * K;
    }

    float acc0[8], acc1[8];
#pragma unroll
    for (int i = 0; i < 8; i++) { acc0[i] = 0.f; acc1[i] = 0.f; }

#pragma unroll 4
    for (int k = 0; k < K; k += 4) {
        float2 wv0 = *(const float2*)&ws[(k + 0) * 64 + lane * 2];
        float2 wv1 = *(const float2*)&ws[(k + 1) * 64 + lane * 2];
        float2 wv2 = *(const float2*)&ws[(k + 2) * 64 + lane * 2];
        float2 wv3 = *(const float2*)&ws[(k + 3) * 64 + lane * 2];
#pragma unroll
        for (int i = 0; i < 8; i++) {
            float4 xv = *(const float4*)(xp[i] + k);
            acc0[i] = fmaf(xv.x, wv0.x, acc0[i]); acc1[i] = fmaf(xv.x, wv0.y, acc1[i]);
            acc0[i] = fmaf(xv.y, wv1.x, acc0[i]); acc1[i] = fmaf(xv.y, wv1.y, acc1[i]);
            acc0[i] = fmaf(xv.z, wv2.x, acc0[i]); acc1[i] = fmaf(xv.z, wv2.y, acc1[i]);
            acc0[i] = fmaf(xv.w, wv3.x, acc0[i]); acc1[i] = fmaf(xv.w, wv3.y, acc1[i]);
        }
    }

#pragma unroll
    for (int i = 0; i < 8; i++) {
        int r = row0 + i;
        if (r < NN)
            Y[(size_t)r * 32 + lane] = __floats2half2_rn(acc0[i], acc1[i]);
    }
}

// ---------------- aggregation: warp per node, 4-edge unroll ----------------
__global__ void __launch_bounds__(256) agg_kernel(int dst_sel,
                                                  const float* __restrict__ bias) {
    int gw   = (blockIdx.x * 256 + threadIdx.x) >> 5;
    int lane = threadIdx.x & 31;
    if (gw >= NN) return;

    const __half2* hl = (const __half2*)g_hlin;
    float*         hout = buf_sel(dst_sel);

    int beg = g_rowptr[gw], end = g_rowptr[gw + 1];
    float a0 = 0.f, a1 = 0.f, c0 = 0.f, c1 = 0.f;

    int e = beg;
    for (; e + 4 <= end; e += 4) {
        int2 E0 = g_edge[e];
        int2 E1 = g_edge[e + 1];
        int2 E2 = g_edge[e + 2];
        int2 E3 = g_edge[e + 3];
        float2 h0 = __half22float2(hl[(size_t)E0.x * 32 + lane]);
        float2 h1 = __half22float2(hl[(size_t)E1.x * 32 + lane]);
        float2 h2 = __half22float2(hl[(size_t)E2.x * 32 + lane]);
        float2 h3 = __half22float2(hl[(size_t)E3.x * 32 + lane]);
        float w0 = __int_as_float(E0.y), w1 = __int_as_float(E1.y);
        float w2 = __int_as_float(E2.y), w3 = __int_as_float(E3.y);
        a0 = fmaf(w0, h0.x, a0); a1 = fmaf(w0, h0.y, a1);
        c0 = fmaf(w1, h1.x, c0); c1 = fmaf(w1, h1.y, c1);
        a0 = fmaf(w2, h2.x, a0); a1 = fmaf(w2, h2.y, a1);
        c0 = fmaf(w3, h3.x, c0); c1 = fmaf(w3, h3.y, c1);
    }
    for (; e < end; e++) {
        int2 E0 = g_edge[e];
        float2 h0 = __half22float2(hl[(size_t)E0.x * 32 + lane]);
        float w0 = __int_as_float(E0.y);
        a0 = fmaf(w0, h0.x, a0); a1 = fmaf(w0, h0.y, a1);
    }
    a0 += c0; a1 += c1;

    float b0 = bias[lane * 2], b1 = bias[lane * 2 + 1];
    float2 o;
    o.x = fmaxf(a0 + b0, 0.f);
    o.y = fmaxf(a1 + b1, 0.f);
    *(float2*)&hout[(size_t)gw * 64 + lane * 2] = o;
}

// ---------------- final: out = [h0|h1|h2] @ Wlin + blin (pad fused via smem) ----------------
__global__ void __launch_bounds__(256) final_kernel(const float* __restrict__ Wlin,
                                                    const float* __restrict__ blin,
                                                    float* __restrict__ out) {
    __shared__ float ws[192 * 64];   // 48 KB: Wlin padded 40 -> 64 cols
    int tid = threadIdx.x;
    for (int i = tid; i < 192 * 64; i += 256) {
        int k = i >> 6, c = i & 63;
        ws[i] = (c < OUTD) ? Wlin[k * OUTD + c] : 0.f;
    }
    __syncthreads();

    int w = tid >> 5, lane = tid & 31;
    int row0 = blockIdx.x * 64 + w * 8;

    int rr[8];
#pragma unroll
    for (int i = 0; i < 8; i++) {
        int r = row0 + i;
        rr[i] = (r < NN) ? r : NN - 1;
    }

    float acc0[8], acc1[8];
#pragma unroll
    for (int i = 0; i < 8; i++) { acc0[i] = 0.f; acc1[i] = 0.f; }

#pragma unroll 1
    for (int l = 0; l < 3; l++) {
        const float* Hp = (l == 0) ? g_h0 : (l == 1) ? g_h1 : g_h2;
        const float* wp = ws + l * 64 * 64;
#pragma unroll 4
        for (int k = 0; k < 64; k += 4) {
            float2 wv0 = *(const float2*)&wp[(k + 0) * 64 + lane * 2];
            float2 wv1 = *(const float2*)&wp[(k + 1) * 64 + lane * 2];
            float2 wv2 = *(const float2*)&wp[(k + 2) * 64 + lane * 2];
            float2 wv3 = *(const float2*)&wp[(k + 3) * 64 + lane * 2];
#pragma unroll
            for (int i = 0; i < 8; i++) {
                float4 xv = *(const float4*)&Hp[(size_t)rr[i] * 64 + k];
                acc0[i] = fmaf(xv.x, wv0.x, acc0[i]); acc1[i] = fmaf(xv.x, wv0.y, acc1[i]);
                acc0[i] = fmaf(xv.y, wv1.x, acc0[i]); acc1[i] = fmaf(xv.y, wv1.y, acc1[i]);
                acc0[i] = fmaf(xv.z, wv2.x, acc0[i]); acc1[i] = fmaf(xv.z, wv2.y, acc1[i]);
                acc0[i] = fmaf(xv.w, wv3.x, acc0[i]); acc1[i] = fmaf(xv.w, wv3.y, acc1[i]);
            }
        }
    }

    int c = lane * 2;
    if (c < OUTD) {
        float b0 = blin[c], b1 = blin[c + 1];
#pragma unroll
        for (int i = 0; i < 8; i++) {
            int r = row0 + i;
            if (r < NN) {
                float2 o; o.x = acc0[i] + b0; o.y = acc1[i] + b1;
                *(float2*)&out[(size_t)r * OUTD + c] = o;
            }
        }
    }
}

// ---------------- launch ----------------
extern "C" void kernel_launch(void* const* d_in, const int* in_sizes, int n_in,
                              void* d_out, int out_size) {
    const float* x    = (const float*)d_in[0];
    const int*   ei32 = (const int*)d_in[1];
    const float* ew   = (const float*)d_in[2];
    const float* W1 = (const float*)d_in[3];
    const float* b1 = (const float*)d_in[4];
    const float* W2 = (const float*)d_in[5];
    const float* b2 = (const float*)d_in[6];
    const float* W3 = (const float*)d_in[7];
    const float* b3 = (const float*)d_in[8];
    const float* Wl = (const float*)d_in[9];
    const float* bl = (const float*)d_in[10];
    float* out = (float*)d_out;

    const int AB = (NN * 32 + 255) / 256;     // 6250

    zero_detect_kernel<<<NBLK, 256>>>(ei32);   // launch 0
    hist_kernel<<<HB, 256>>>(ei32);            // launch 1
    scanA_kernel<<<NBLK, 256>>>();             // launch 2
    scanB_kernel<<<NBLK, 256>>>();             // launch 3
    fill_kernel<<<HB, 256>>>(ei32, ew);        // launch 4

    gemm64_kernel<IND><<<GB, 256>>>(x, -1, W1);   // launch 5  (ncu -s 5 profiles this)
    agg_kernel<<<AB, 256>>>(1, b1);

    gemm64_kernel<HID><<<GB, 256>>>(nullptr, 1, W2);
    agg_kernel<<<AB, 256>>>(2, b2);

    gemm64_kernel<HID><<<GB, 256>>>(nullptr, 2, W3);
    agg_kernel<<<AB, 256>>>(3, b3);

    final_kernel<<<GB, 256>>>(Wl, bl, out);
}

// round 8
// speedup vs baseline: 2.8726x; 1.9769x over previous
#include <cuda_runtime.h>
#include <cuda_fp16.h>

#define NN   50000
#define EE   800000
#define HID  64
#define IND  128
#define OUTD 40
#define NBLK ((NN + 255) / 256)   // 196 scan blocks
#define GB   ((NN + 63) / 64)     // 782 mma-gemm blocks (64 rows each)
#define HB   ((EE + 255) / 256)   // 3125 edge blocks

// ---------------- device scratch (no allocations allowed) ----------------
__device__ __half g_xh[NN * IND];       // x converted to fp16
__device__ __half g_hlin[NN * HID];     // gemm output (pre-aggregation), fp16
__device__ __half g_h0[NN * HID];       // layer outputs (JK cat members), fp16
__device__ __half g_h1[NN * HID];
__device__ __half g_h2[NN * HID];
__device__ __half g_w1[IND * 64];       // fp16 weights
__device__ __half g_w2[HID * 64];
__device__ __half g_w3[HID * 64];
__device__ __half g_wl[192 * 64];       // Wlin padded 40 -> 64 cols, fp16
__device__ int   g_rowptr[NN + 1];
__device__ int   g_cnt[NN];
__device__ int   g_bsum[NBLK];
__device__ int2  g_edge[EE];            // (src, weight-bits) grouped by dst
__device__ int   g_is64;

__device__ __forceinline__ const __half* hsel(int s) {
    switch (s) {
        case 0:  return g_xh;
        case 1:  return g_h0;
        case 2:  return g_h1;
        default: return g_h2;
    }
}
__device__ __forceinline__ __half* hdst(int s) {
    switch (s) {
        case 1:  return g_h0;
        case 2:  return g_h1;
        default: return g_h2;
    }
}
__device__ __forceinline__ const __half* wsel(int s) {
    switch (s) {
        case 1:  return g_w1;
        case 2:  return g_w2;
        default: return g_w3;
    }
}

__device__ __forceinline__ int clampN(int v) {
    return (v < 0) ? 0 : ((v >= NN) ? NN - 1 : v);
}
__device__ __forceinline__ int edge_at(const int* __restrict__ p32, int row, int e, int is64) {
    long long idx = (long long)row * EE + e;
    return is64 ? p32[2 * idx] : p32[idx];
}

__device__ __forceinline__ unsigned smem_u32(const void* p) {
    return (unsigned)__cvta_generic_to_shared(p);
}
__device__ __forceinline__ void ldm_x4(unsigned& r0, unsigned& r1, unsigned& r2, unsigned& r3, unsigned a) {
    asm volatile("ldmatrix.sync.aligned.m8n8.x4.shared.b16 {%0,%1,%2,%3}, [%4];"
                 : "=r"(r0), "=r"(r1), "=r"(r2), "=r"(r3) : "r"(a));
}
__device__ __forceinline__ void ldm_x4_t(unsigned& r0, unsigned& r1, unsigned& r2, unsigned& r3, unsigned a) {
    asm volatile("ldmatrix.sync.aligned.m8n8.x4.trans.shared.b16 {%0,%1,%2,%3}, [%4];"
                 : "=r"(r0), "=r"(r1), "=r"(r2), "=r"(r3) : "r"(a));
}
__device__ __forceinline__ void mma16816(float* c, unsigned a0, unsigned a1, unsigned a2, unsigned a3,
                                         unsigned b0, unsigned b1) {
    asm volatile("mma.sync.aligned.m16n8k16.row.col.f32.f16.f16.f32 "
                 "{%0,%1,%2,%3}, {%4,%5,%6,%7}, {%8,%9}, {%0,%1,%2,%3};"
                 : "+f"(c[0]), "+f"(c[1]), "+f"(c[2]), "+f"(c[3])
                 : "r"(a0), "r"(a1), "r"(a2), "r"(a3), "r"(b0), "r"(b1));
}

// ---------------- prep: fp32 -> fp16 conversions ----------------
#define XV4 (NN * IND / 4)          // 1,600,000 float4s
#define PREPEXT (IND*64 + HID*64 + HID*64 + 192*64)
__global__ void prep_kernel(const float* __restrict__ x,
                            const float* __restrict__ W1,
                            const float* __restrict__ W2,
                            const float* __restrict__ W3,
                            const float* __restrict__ Wl) {
    int idx = blockIdx.x * 256 + threadIdx.x;
    if (idx < XV4) {
        float4 v = ((const float4*)x)[idx];
        __half2* xo = (__half2*)g_xh;
        xo[idx * 2 + 0] = __floats2half2_rn(v.x, v.y);
        xo[idx * 2 + 1] = __floats2half2_rn(v.z, v.w);
        return;
    }
    int j = idx - XV4;
    if (j < IND * 64) { g_w1[j] = __float2half_rn(W1[j]); return; }
    j -= IND * 64;
    if (j < HID * 64) { g_w2[j] = __float2half_rn(W2[j]); return; }
    j -= HID * 64;
    if (j < HID * 64) { g_w3[j] = __float2half_rn(W3[j]); return; }
    j -= HID * 64;
    if (j < 192 * 64) {
        int k = j >> 6, c = j & 63;
        g_wl[j] = (c < OUTD) ? __float2half_rn(Wl[k * OUTD + c]) : __float2half_rn(0.f);
    }
}

// ---------------- zero counters + dtype detect ----------------
__global__ void zero_detect_kernel(const int* __restrict__ p32) {
    int i = blockIdx.x * blockDim.x + threadIdx.x;
    if (i < NN) g_cnt[i] = 0;
    if (blockIdx.x == 0 && threadIdx.x < 32) {
        int lane = threadIdx.x;
        int any = p32[2 * lane + 1] | p32[2 * (lane + 32) + 1];
        unsigned nz = __ballot_sync(0xFFFFFFFFu, any != 0);
        if (lane == 0) g_is64 = (nz == 0) ? 1 : 0;
    }
}

__global__ void hist_kernel(const int* __restrict__ ei32) {
    int e = blockIdx.x * blockDim.x + threadIdx.x;
    if (e < EE) {
        int d = clampN(edge_at(ei32, 1, e, g_is64));
        atomicAdd(&g_cnt[d], 1);
    }
}

// ---------------- scan ----------------
__device__ __forceinline__ int block_excl_scan_256(int v, int tid, int* wsum) {
    int lane = tid & 31, w = tid >> 5;
    int x = v;
#pragma unroll
    for (int o = 1; o < 32; o <<= 1) {
        int y = __shfl_up_sync(0xFFFFFFFFu, x, o);
        if (lane >= o) x += y;
    }
    if (lane == 31) wsum[w] = x;
    __syncthreads();
    if (w == 0) {
        int s = (lane < 8) ? wsum[lane] : 0;
#pragma unroll
        for (int o = 1; o < 8; o <<= 1) {
            int y = __shfl_up_sync(0xFFFFFFFFu, s, o);
            if (lane >= o) s += y;
        }
        if (lane < 8) wsum[lane] = s;
    }
    __syncthreads();
    int incl = x + ((w > 0) ? wsum[w - 1] : 0);
    return incl - v;
}

__global__ void __launch_bounds__(256) scanA_kernel() {
    int i = blockIdx.x * 256 + threadIdx.x;
    int v = (i < NN) ? g_cnt[i] : 0;
#pragma unroll
    for (int o = 16; o > 0; o >>= 1) v += __shfl_down_sync(0xFFFFFFFFu, v, o);
    __shared__ int wsum[8];
    if ((threadIdx.x & 31) == 0) wsum[threadIdx.x >> 5] = v;
    __syncthreads();
    if (threadIdx.x == 0) {
        int s = 0;
#pragma unroll
        for (int w = 0; w < 8; w++) s += wsum[w];
        g_bsum[blockIdx.x] = s;
    }
}

__global__ void __launch_bounds__(256) scanB_kernel() {
    __shared__ int wsum[8];
    __shared__ int blk_off;
    int tid = threadIdx.x;

    int v = (tid < NBLK) ? g_bsum[tid] : 0;
    int excl = block_excl_scan_256(v, tid, wsum);
    if (tid == blockIdx.x) blk_off = excl;
    if (blockIdx.x == 0 && tid == NBLK - 1) g_rowptr[NN] = excl + v;
    __syncthreads();

    int i = blockIdx.x * 256 + tid;
    int c = (i < NN) ? g_cnt[i] : 0;
    int ex2 = block_excl_scan_256(c, tid, wsum);
    if (i < NN) {
        g_rowptr[i] = blk_off + ex2;
        g_cnt[i] = 0;
    }
}

__global__ void fill_kernel(const int* __restrict__ ei32,
                            const float* __restrict__ ew) {
    int e = blockIdx.x * blockDim.x + threadIdx.x;
    if (e < EE) {
        int is64 = g_is64;
        int d = clampN(edge_at(ei32, 1, e, is64));
        int s = clampN(edge_at(ei32, 0, e, is64));
        int pos = g_rowptr[d] + atomicAdd(&g_cnt[d], 1);
        g_edge[pos] = make_int2(s, __float_as_int(ew[e]));
    }
}

// ---------------- tensor-core GEMM: g_hlin[N,64] = X[N,K] @ W[K,64] (all fp16) ----------------
// 128 threads = 4 warps; block tile 64 rows x 64 cols; warp = 16 rows x 64 cols.
template <int K>
__global__ void __launch_bounds__(128) gemm_mma_kernel(int src_sel, int w_sel) {
    constexpr int XS = K + 8;          // smem row stride (halves), 16B-aligned, bank-rotated
    __shared__ __half Xs[64 * XS];
    __shared__ __half Ws[K * 72];

    int tid = threadIdx.x, warp = tid >> 5, lane = tid & 31;
    int row0 = blockIdx.x * 64;

    const __half* X = hsel(src_sel);
    const __half* Wp = wsel(w_sel);

    constexpr int NV = K / 8;          // uint4 per X row
    for (int i = tid; i < 64 * NV; i += 128) {
        int r = i / NV, c = i % NV;
        int gr = row0 + r; if (gr >= NN) gr = NN - 1;
        *(uint4*)&Xs[r * XS + c * 8] = *(const uint4*)&X[(size_t)gr * K + c * 8];
    }
    for (int i = tid; i < K * 8; i += 128) {
        int r = i >> 3, c = i & 7;
        *(uint4*)&Ws[r * 72 + c * 8] = *(const uint4*)&Wp[r * 64 + c * 8];
    }
    __syncthreads();

    int wr = warp * 16;
    float acc[8][4];
#pragma unroll
    for (int g = 0; g < 8; g++) { acc[g][0] = acc[g][1] = acc[g][2] = acc[g][3] = 0.f; }

    unsigned xb = smem_u32(Xs), wb = smem_u32(Ws);
    int arow = wr + ((lane >> 3) & 1) * 8 + (lane & 7);
    int acol8 = (lane >> 4) * 8;
    int brow8 = ((lane >> 3) & 1) * 8 + (lane & 7);

#pragma unroll
    for (int kk = 0; kk < K / 16; kk++) {
        unsigned a0, a1, a2, a3;
        ldm_x4(a0, a1, a2, a3, xb + (arow * XS + kk * 16 + acol8) * 2);
#pragma unroll
        for (int jn = 0; jn < 4; jn++) {
            unsigned b0, b1, b2, b3;
            ldm_x4_t(b0, b1, b2, b3, wb + ((kk * 16 + brow8) * 72 + jn * 16 + acol8) * 2);
            mma16816(acc[jn * 2 + 0], a0, a1, a2, a3, b0, b1);
            mma16816(acc[jn * 2 + 1], a0, a1, a2, a3, b2, b3);
        }
    }

    __half2* hl = (__half2*)g_hlin;
    int g = lane >> 2, q = lane & 3;
#pragma unroll
    for (int gn = 0; gn < 8; gn++) {
        int r0 = row0 + wr + g, r1 = r0 + 8;
        int cidx = gn * 4 + q;   // half2 column index
        if (r0 < NN) hl[(size_t)r0 * 32 + cidx] = __floats2half2_rn(acc[gn][0], acc[gn][1]);
        if (r1 < NN) hl[(size_t)r1 * 32 + cidx] = __floats2half2_rn(acc[gn][2], acc[gn][3]);
    }
}

// ---------------- aggregation: warp per node, 4-edge unroll, fp16 in/out ----------------
__global__ void __launch_bounds__(256) agg_kernel(int dst_sel,
                                                  const float* __restrict__ bias) {
    int gw   = (blockIdx.x * 256 + threadIdx.x) >> 5;
    int lane = threadIdx.x & 31;
    if (gw >= NN) return;

    const __half2* hl = (const __half2*)g_hlin;
    __half2*       hout = (__half2*)hdst(dst_sel);

    int beg = g_rowptr[gw], end = g_rowptr[gw + 1];
    float a0 = 0.f, a1 = 0.f, c0 = 0.f, c1 = 0.f;

    int e = beg;
    for (; e + 4 <= end; e += 4) {
        int2 E0 = g_edge[e];
        int2 E1 = g_edge[e + 1];
        int2 E2 = g_edge[e + 2];
        int2 E3 = g_edge[e + 3];
        float2 h0 = __half22float2(hl[(size_t)E0.x * 32 + lane]);
        float2 h1 = __half22float2(hl[(size_t)E1.x * 32 + lane]);
        float2 h2 = __half22float2(hl[(size_t)E2.x * 32 + lane]);
        float2 h3 = __half22float2(hl[(size_t)E3.x * 32 + lane]);
        float w0 = __int_as_float(E0.y), w1 = __int_as_float(E1.y);
        float w2 = __int_as_float(E2.y), w3 = __int_as_float(E3.y);
        a0 = fmaf(w0, h0.x, a0); a1 = fmaf(w0, h0.y, a1);
        c0 = fmaf(w1, h1.x, c0); c1 = fmaf(w1, h1.y, c1);
        a0 = fmaf(w2, h2.x, a0); a1 = fmaf(w2, h2.y, a1);
        c0 = fmaf(w3, h3.x, c0); c1 = fmaf(w3, h3.y, c1);
    }
    for (; e < end; e++) {
        int2 E0 = g_edge[e];
        float2 h0 = __half22float2(hl[(size_t)E0.x * 32 + lane]);
        float w0 = __int_as_float(E0.y);
        a0 = fmaf(w0, h0.x, a0); a1 = fmaf(w0, h0.y, a1);
    }
    a0 += c0; a1 += c1;

    float b0 = bias[lane * 2], b1 = bias[lane * 2 + 1];
    hout[(size_t)gw * 32 + lane] =
        __floats2half2_rn(fmaxf(a0 + b0, 0.f), fmaxf(a1 + b1, 0.f));
}

// ---------------- final: out[N,40] = [h0|h1|h2] @ Wlin + blin (tensor cores) ----------------
__global__ void __launch_bounds__(128) final_mma_kernel(const float* __restrict__ blin,
                                                        float* __restrict__ out) {
    constexpr int XS = 72;
    __shared__ __half Xs[64 * XS];
    __shared__ __half Ws[192 * 72];

    int tid = threadIdx.x, warp = tid >> 5, lane = tid & 31;
    int row0 = blockIdx.x * 64;

    for (int i = tid; i < 192 * 8; i += 128) {
        int r = i >> 3, c = i & 7;
        *(uint4*)&Ws[r * 72 + c * 8] = *(const uint4*)&g_wl[r * 64 + c * 8];
    }

    int wr = warp * 16;
    float acc[8][4];
#pragma unroll
    for (int g = 0; g < 8; g++) { acc[g][0] = acc[g][1] = acc[g][2] = acc[g][3] = 0.f; }

    unsigned xb = smem_u32(Xs), wb = smem_u32(Ws);
    int arow = wr + ((lane >> 3) & 1) * 8 + (lane & 7);
    int acol8 = (lane >> 4) * 8;
    int brow8 = ((lane >> 3) & 1) * 8 + (lane & 7);

#pragma unroll 1
    for (int l = 0; l < 3; l++) {
        const __half* H = hsel(1 + l);
        __syncthreads();   // previous segment's ldmatrix done
        for (int i = tid; i < 64 * 8; i += 128) {
            int r = i >> 3, c = i & 7;
            int gr = row0 + r; if (gr >= NN) gr = NN - 1;
            *(uint4*)&Xs[r * XS + c * 8] = *(const uint4*)&H[(size_t)gr * 64 + c * 8];
        }
        __syncthreads();

#pragma unroll
        for (int kk = 0; kk < 4; kk++) {
            unsigned a0, a1, a2, a3;
            ldm_x4(a0, a1, a2, a3, xb + (arow * XS + kk * 16 + acol8) * 2);
#pragma unroll
            for (int jn = 0; jn < 4; jn++) {
                unsigned b0, b1, b2, b3;
                ldm_x4_t(b0, b1, b2, b3,
                         wb + ((l * 64 + kk * 16 + brow8) * 72 + jn * 16 + acol8) * 2);
                mma16816(acc[jn * 2 + 0], a0, a1, a2, a3, b0, b1);
                mma16816(acc[jn * 2 + 1], a0, a1, a2, a3, b2, b3);
            }
        }
    }

    int g = lane >> 2, q = lane & 3;
#pragma unroll
    for (int gn = 0; gn < 5; gn++) {       // cols 0..39 only
        int col = gn * 8 + q * 2;
        if (col >= OUTD) continue;
        float b0 = blin[col], b1 = blin[col + 1];
        int r0 = row0 + wr + g, r1 = r0 + 8;
        if (r0 < NN) {
            float2 o; o.x = acc[gn][0] + b0; o.y = acc[gn][1] + b1;
            *(float2*)&out[(size_t)r0 * OUTD + col] = o;
        }
        if (r1 < NN) {
            float2 o; o.x = acc[gn][2] + b0; o.y = acc[gn][3] + b1;
            *(float2*)&out[(size_t)r1 * OUTD + col] = o;
        }
    }
}

// ---------------- launch ----------------
extern "C" void kernel_launch(void* const* d_in, const int* in_sizes, int n_in,
                              void* d_out, int out_size) {
    const float* x    = (const float*)d_in[0];
    const int*   ei32 = (const int*)d_in[1];
    const float* ew   = (const float*)d_in[2];
    const float* W1 = (const float*)d_in[3];
    const float* b1 = (const float*)d_in[4];
    const float* W2 = (const float*)d_in[5];
    const float* b2 = (const float*)d_in[6];
    const float* W3 = (const float*)d_in[7];
    const float* b3 = (const float*)d_in[8];
    const float* Wl = (const float*)d_in[9];
    const float* bl = (const float*)d_in[10];
    float* out = (float*)d_out;

    const int AB = (NN * 32 + 255) / 256;     // 6250
    const int PREPB = (XV4 + PREPEXT + 255) / 256;

    prep_kernel<<<PREPB, 256>>>(x, W1, W2, W3, Wl);
    zero_detect_kernel<<<NBLK, 256>>>(ei32);
    hist_kernel<<<HB, 256>>>(ei32);
    scanA_kernel<<<NBLK, 256>>>();
    scanB_kernel<<<NBLK, 256>>>();
    fill_kernel<<<HB, 256>>>(ei32, ew);

    gemm_mma_kernel<IND><<<GB, 128>>>(0, 1);
    agg_kernel<<<AB, 256>>>(1, b1);

    gemm_mma_kernel<HID><<<GB, 128>>>(1, 2);
    agg_kernel<<<AB, 256>>>(2, b2);

    gemm_mma_kernel<HID><<<GB, 128>>>(2, 3);
    agg_kernel<<<AB, 256>>>(3, b3);

    final_mma_kernel<<<GB, 128>>>(bl, out);
}